// round 3
// baseline (speedup 1.0000x reference)
#include <cuda_runtime.h>
#include <math.h>
#include <stdint.h>

// Problem dims
#define Bv    2
#define NQv   1024
#define NKVv  2048
#define Dv    1024
#define Hv    16
#define DHv   64
#define Ev    8
#define FFv   4096
#define TQ    (Bv*NQv)    // 2048 query tokens
#define TKV   (Bv*NKVv)   // 4096 kv tokens
#define MAXTOK 2048       // max tokens per expert (each token -> 2 distinct experts)

// ---------------- scratch (device globals; no allocation) ----------------
__device__ float g_x[TQ*Dv];                  // residual stream
__device__ float g_ln1[TQ*Dv];                // ln output (q / xs / xm)
__device__ float g_lnkv[TKV*Dv];              // ln(kv)
__device__ float g_qp[TQ*Dv];                 // CA q proj
__device__ float g_kvp[TKV*2048];             // CA: [4096,2048] k|v ; SA: [2048,3072] q|k|v (fits)
__device__ float g_scores[(size_t)Bv*Hv*NQv*NKVv]; // 256MB, reused CA/SA
__device__ float g_ao[TQ*Dv];                 // attention head-concat output
__device__ float g_h[(size_t)TQ*2*FFv];       // MoE hidden per slot
__device__ float g_eo[(size_t)TQ*2*Dv];       // MoE expert output per slot
__device__ float g_probs[TQ*2];
__device__ int   g_counts[Ev];
__device__ int   g_elist[Ev*MAXTOK];          // slot ids (t*2+k) per expert

// ---------------- layernorm ----------------
__global__ void ln_k(const float* __restrict__ x, float* __restrict__ y,
                     const float* __restrict__ g, const float* __restrict__ b) {
    long row = blockIdx.x;
    const float* xr = x + row * 1024;
    float* yr = y + row * 1024;
    __shared__ float sm[1024];
    __shared__ float red[256];
    int tid = threadIdx.x;
    float s = 0.f;
    #pragma unroll
    for (int i = 0; i < 4; i++) { float v = xr[tid + (i<<8)]; sm[tid + (i<<8)] = v; s += v; }
    red[tid] = s; __syncthreads();
    for (int st = 128; st > 0; st >>= 1) { if (tid < st) red[tid] += red[tid + st]; __syncthreads(); }
    float mean = red[0] * (1.0f/1024.0f); __syncthreads();
    float s2 = 0.f;
    #pragma unroll
    for (int i = 0; i < 4; i++) { float d = sm[tid + (i<<8)] - mean; s2 += d*d; }
    red[tid] = s2; __syncthreads();
    for (int st = 128; st > 0; st >>= 1) { if (tid < st) red[tid] += red[tid + st]; __syncthreads(); }
    float var = red[0] * (1.0f/1024.0f);
    float rstd = rsqrtf(var + 1e-5f);
    #pragma unroll
    for (int i = 0; i < 4; i++) { int c = tid + (i<<8); yr[c] = (sm[c]-mean)*rstd*g[c] + b[c]; }
}

// ---------------- softmax over rows ----------------
__global__ void softmax_k(float* __restrict__ S, int L) {
    float* r = S + (size_t)blockIdx.x * L;
    int tid = threadIdx.x;
    __shared__ float red[256];
    int cnt = L >> 8; // 4 or 8
    float v[8];
    float mx = -3.4e38f;
    for (int i = 0; i < cnt; i++) { v[i] = r[tid + (i<<8)]; mx = fmaxf(mx, v[i]); }
    red[tid] = mx; __syncthreads();
    for (int st = 128; st > 0; st >>= 1) { if (tid < st) red[tid] = fmaxf(red[tid], red[tid+st]); __syncthreads(); }
    mx = red[0]; __syncthreads();
    float sum = 0.f;
    for (int i = 0; i < cnt; i++) { v[i] = expf(v[i]-mx); sum += v[i]; }
    red[tid] = sum; __syncthreads();
    for (int st = 128; st > 0; st >>= 1) { if (tid < st) red[tid] += red[tid+st]; __syncthreads(); }
    float inv = 1.0f / red[0];
    for (int i = 0; i < cnt; i++) r[tid + (i<<8)] = v[i]*inv;
}

// ---------------- generic tiled GEMM ----------------
// C[M,N] = alpha * A[M,K] * op(B) + bias + res
// BT=true : B is [N,K] row-major (weights-as-W, scores QK^T)
// BT=false: B is [K,N] row-major (P@V, MoE)
// batch: z = blockIdx.z ; outer = z/inner, in = z%inner, offsets applied per operand
template<bool BT>
__global__ __launch_bounds__(256) void gemm_k(
    const float* __restrict__ A, int lda, long long sAo, long long sAi,
    const float* __restrict__ B, int ldb, long long sBo, long long sBi,
    float* __restrict__ C, int ldc, long long sCo, long long sCi,
    int M, int N, int K, int inner,
    const float* __restrict__ bias, float alpha, const float* __restrict__ res)
{
    int z = blockIdx.z;
    int zo = z / inner, zi = z - zo * inner;
    A += zo * sAo + zi * sAi;
    B += zo * sBo + zi * sBi;
    C += zo * sCo + zi * sCi;
    if (res) res += zo * sCo + zi * sCi;

    __shared__ float As[16][68];
    __shared__ float Bs[16][68];
    int tid = threadIdx.x;
    int tx = tid & 15, ty = tid >> 4;
    int m0 = blockIdx.y * 64, n0 = blockIdx.x * 64;
    float acc[4][4] = {};

    for (int k0 = 0; k0 < K; k0 += 16) {
        #pragma unroll
        for (int i = 0; i < 4; i++) {
            int idx = tid + (i << 8);
            int m = idx >> 4, kk = idx & 15;
            int gm = m0 + m;
            As[kk][m] = (gm < M) ? A[(long long)gm * lda + k0 + kk] : 0.f;
        }
        #pragma unroll
        for (int i = 0; i < 4; i++) {
            int idx = tid + (i << 8);
            if (BT) {
                int n = idx >> 4, kk = idx & 15;
                Bs[kk][n] = B[(long long)(n0 + n) * ldb + k0 + kk];
            } else {
                int kk = idx >> 6, n = idx & 63;
                Bs[kk][n] = B[(long long)(k0 + kk) * ldb + n0 + n];
            }
        }
        __syncthreads();
        #pragma unroll
        for (int kk = 0; kk < 16; kk++) {
            float a[4], b[4];
            #pragma unroll
            for (int i = 0; i < 4; i++) a[i] = As[kk][ty*4 + i];
            #pragma unroll
            for (int j = 0; j < 4; j++) b[j] = Bs[kk][tx*4 + j];
            #pragma unroll
            for (int i = 0; i < 4; i++)
                #pragma unroll
                for (int j = 0; j < 4; j++)
                    acc[i][j] += a[i] * b[j];
        }
        __syncthreads();
    }
    #pragma unroll
    for (int i = 0; i < 4; i++) {
        int gm = m0 + ty*4 + i;
        if (gm >= M) continue;
        #pragma unroll
        for (int j = 0; j < 4; j++) {
            int gn = n0 + tx*4 + j;
            float v = alpha * acc[i][j];
            if (bias) v += bias[gn];
            if (res)  v += res[(long long)gm * ldc + gn];
            C[(long long)gm * ldc + gn] = v;
        }
    }
}

// ---------------- JAX threefry2x32 / normal reproduction ----------------
__device__ __forceinline__ void threefry42(unsigned c0, unsigned c1, unsigned& o0, unsigned& o1) {
    const unsigned k0 = 0u, k1 = 42u;
    const unsigned k2 = 0x1BD11BDAu ^ k0 ^ k1;
    unsigned x0 = c0 + k0, x1 = c1 + k1;
#define TF_R(r) { x0 += x1; x1 = (x1 << r) | (x1 >> (32 - r)); x1 ^= x0; }
    TF_R(13) TF_R(15) TF_R(26) TF_R(6)   x0 += k1; x1 += k2 + 1u;
    TF_R(17) TF_R(29) TF_R(16) TF_R(24)  x0 += k2; x1 += k0 + 2u;
    TF_R(13) TF_R(15) TF_R(26) TF_R(6)   x0 += k0; x1 += k1 + 3u;
    TF_R(17) TF_R(29) TF_R(16) TF_R(24)  x0 += k1; x1 += k2 + 4u;
    TF_R(13) TF_R(15) TF_R(26) TF_R(6)   x0 += k2; x1 += k0 + 5u;
#undef TF_R
    o0 = x0; o1 = x1;
}

// XLA ErfInv32 polynomial (mul/add, no fma, matching XLA codegen)
__device__ __forceinline__ float erfinv_f(float x) {
    float w = -log1pf(__fmul_rn(-x, x));
    float p;
    if (w < 5.0f) {
        w = __fadd_rn(w, -2.5f);
        p = 2.81022636e-08f;
        p = __fadd_rn(__fmul_rn(p, w),  3.43273939e-07f);
        p = __fadd_rn(__fmul_rn(p, w), -3.5233877e-06f);
        p = __fadd_rn(__fmul_rn(p, w), -4.39150654e-06f);
        p = __fadd_rn(__fmul_rn(p, w),  0.00021858087f);
        p = __fadd_rn(__fmul_rn(p, w), -0.00125372503f);
        p = __fadd_rn(__fmul_rn(p, w), -0.00417768164f);
        p = __fadd_rn(__fmul_rn(p, w),  0.246640727f);
        p = __fadd_rn(__fmul_rn(p, w),  1.50140941f);
    } else {
        w = __fadd_rn(sqrtf(w), -3.0f);
        p = -0.000200214257f;
        p = __fadd_rn(__fmul_rn(p, w),  0.000100950558f);
        p = __fadd_rn(__fmul_rn(p, w),  0.00134934322f);
        p = __fadd_rn(__fmul_rn(p, w), -0.00367342844f);
        p = __fadd_rn(__fmul_rn(p, w),  0.00573950773f);
        p = __fadd_rn(__fmul_rn(p, w), -0.0076224613f);
        p = __fadd_rn(__fmul_rn(p, w),  0.00943887047f);
        p = __fadd_rn(__fmul_rn(p, w),  1.00167406f);
        p = __fadd_rn(__fmul_rn(p, w),  2.83297682f);
    }
    return __fmul_rn(p, x);
}

// normal sample for flat index i of shape [2,1024,8] (16384 total), key(42).
// MODERN JAX (jax_threefry_partitionable=True): counter from iota_2x32_shape
// -> (hi=0, lo=i); for bit_width 32 the two threefry output words are
// XOR-folded: bits = out0 ^ out1.
__device__ __forceinline__ float jax_normal(int i) {
    unsigned o0, o1;
    threefry42(0u, (unsigned)i, o0, o1);   // hi=0 (size < 2^32), lo=i
    unsigned bits = o0 ^ o1;                // XOR fold of 64-bit output
    unsigned fb = (bits >> 9) | 0x3f800000u;
    float u01 = __fadd_rn(__uint_as_float(fb), -1.0f);       // [0,1)
    const float lo = -0.99999994f;                           // nextafter(-1,0)
    float u = __fadd_rn(__fmul_rn(u01, 2.0f), lo);           // (hi-lo) rounds to 2.0f
    u = fmaxf(lo, u);
    return __fmul_rn(1.41421354f, erfinv_f(u));              // sqrt(2)_f32 * erfinv(u)
}

// ---------------- MoE router ----------------
__global__ void zero_counts_k() { if (threadIdx.x < Ev) g_counts[threadIdx.x] = 0; }

__global__ void router_k(const float* __restrict__ xm,
                         const float* __restrict__ rw, const float* __restrict__ rb,
                         const float* __restrict__ nw, const float* __restrict__ nb) {
    int t = blockIdx.x;                 // global token 0..2047  (== b*1024 + tq)
    int tid = threadIdx.x;
    int w = tid >> 5, lane = tid & 31;  // 8 warps -> 8 experts
    __shared__ float sl[8], sn[8];
    const float* xr = xm + (long long)t * 1024;
    const float* rwe = rw + w * 1024;
    const float* nwe = nw + w * 1024;
    float sr = 0.f, s_n = 0.f;
    for (int d = lane; d < 1024; d += 32) {
        float xv = xr[d];
        sr  += xv * rwe[d];
        s_n += xv * nwe[d];
    }
    #pragma unroll
    for (int o = 16; o; o >>= 1) {
        sr  += __shfl_down_sync(0xffffffffu, sr, o);
        s_n += __shfl_down_sync(0xffffffffu, s_n, o);
    }
    if (lane == 0) { sl[w] = sr + rb[w]; sn[w] = s_n + nb[w]; }
    __syncthreads();
    if (tid == 0) {
        float noisy[8];
        #pragma unroll
        for (int e = 0; e < 8; e++) {
            float nrm = jax_normal(t * 8 + e);
            float zz = sn[e];
            float sp = fmaxf(zz, 0.f) + log1pf(expf(-fabsf(zz)));  // softplus = logaddexp(z,0)
            noisy[e] = sl[e] + nrm * sp;
        }
        int i1 = 0;
        #pragma unroll
        for (int e = 1; e < 8; e++) if (noisy[e] > noisy[i1]) i1 = e;
        int i2 = (i1 == 0) ? 1 : 0;
        #pragma unroll
        for (int e = 0; e < 8; e++) if (e != i1 && noisy[e] > noisy[i2]) i2 = e;
        float mx = noisy[i1];
        float e1 = expf(noisy[i1] - mx);
        float e2 = expf(noisy[i2] - mx);
        float Z  = e1 + e2;
        g_probs[2*t]   = e1 / Z;
        g_probs[2*t+1] = e2 / Z;
        int p1 = atomicAdd(&g_counts[i1], 1); g_elist[i1 * MAXTOK + p1] = 2*t;
        int p2 = atomicAdd(&g_counts[i2], 1); g_elist[i2 * MAXTOK + p2] = 2*t + 1;
    }
}

// ---------------- MoE grouped GEMMs ----------------
__global__ __launch_bounds__(256) void moe_gemm1(const float* __restrict__ xm,
                                                 const float* __restrict__ w1,
                                                 const float* __restrict__ b1) {
    int e = blockIdx.z;
    int cnt = g_counts[e];
    int m0 = blockIdx.y * 64;
    if (m0 >= cnt) return;
    int n0 = blockIdx.x * 64;
    __shared__ int slots[64];
    __shared__ float As[16][68];
    __shared__ float Bs[16][68];
    int tid = threadIdx.x;
    if (tid < 64) slots[tid] = (m0 + tid < cnt) ? g_elist[e * MAXTOK + m0 + tid] : -1;
    __syncthreads();
    int tx = tid & 15, ty = tid >> 4;
    const float* Be = w1 + (long long)e * 1024 * 4096;
    float acc[4][4] = {};
    for (int k0 = 0; k0 < 1024; k0 += 16) {
        #pragma unroll
        for (int i = 0; i < 4; i++) {
            int idx = tid + (i << 8);
            int m = idx >> 4, kk = idx & 15;
            int s = slots[m];
            As[kk][m] = (s >= 0) ? xm[(long long)(s >> 1) * 1024 + k0 + kk] : 0.f;
        }
        #pragma unroll
        for (int i = 0; i < 4; i++) {
            int idx = tid + (i << 8);
            int kk = idx >> 6, n = idx & 63;
            Bs[kk][n] = Be[(long long)(k0 + kk) * 4096 + n0 + n];
        }
        __syncthreads();
        #pragma unroll
        for (int kk = 0; kk < 16; kk++) {
            float a[4], b[4];
            #pragma unroll
            for (int i = 0; i < 4; i++) a[i] = As[kk][ty*4 + i];
            #pragma unroll
            for (int j = 0; j < 4; j++) b[j] = Bs[kk][tx*4 + j];
            #pragma unroll
            for (int i = 0; i < 4; i++)
                #pragma unroll
                for (int j = 0; j < 4; j++)
                    acc[i][j] += a[i] * b[j];
        }
        __syncthreads();
    }
    #pragma unroll
    for (int i = 0; i < 4; i++) {
        int s = slots[ty*4 + i];
        if (s < 0) continue;
        #pragma unroll
        for (int j = 0; j < 4; j++) {
            int gn = n0 + tx*4 + j;
            float v = acc[i][j] + b1[e * 4096 + gn];
            v = 0.5f * v * (1.0f + erff(v * 0.70710677f));   // exact gelu
            g_h[(long long)s * 4096 + gn] = v;
        }
    }
}

__global__ __launch_bounds__(256) void moe_gemm2(const float* __restrict__ w2,
                                                 const float* __restrict__ b2) {
    int e = blockIdx.z;
    int cnt = g_counts[e];
    int m0 = blockIdx.y * 64;
    if (m0 >= cnt) return;
    int n0 = blockIdx.x * 64;
    __shared__ int slots[64];
    __shared__ float As[16][68];
    __shared__ float Bs[16][68];
    int tid = threadIdx.x;
    if (tid < 64) slots[tid] = (m0 + tid < cnt) ? g_elist[e * MAXTOK + m0 + tid] : -1;
    __syncthreads();
    int tx = tid & 15, ty = tid >> 4;
    const float* Be = w2 + (long long)e * 4096 * 1024;
    float acc[4][4] = {};
    for (int k0 = 0; k0 < 4096; k0 += 16) {
        #pragma unroll
        for (int i = 0; i < 4; i++) {
            int idx = tid + (i << 8);
            int m = idx >> 4, kk = idx & 15;
            int s = slots[m];
            As[kk][m] = (s >= 0) ? g_h[(long long)s * 4096 + k0 + kk] : 0.f;
        }
        #pragma unroll
        for (int i = 0; i < 4; i++) {
            int idx = tid + (i << 8);
            int kk = idx >> 6, n = idx & 63;
            Bs[kk][n] = Be[(long long)(k0 + kk) * 1024 + n0 + n];
        }
        __syncthreads();
        #pragma unroll
        for (int kk = 0; kk < 16; kk++) {
            float a[4], b[4];
            #pragma unroll
            for (int i = 0; i < 4; i++) a[i] = As[kk][ty*4 + i];
            #pragma unroll
            for (int j = 0; j < 4; j++) b[j] = Bs[kk][tx*4 + j];
            #pragma unroll
            for (int i = 0; i < 4; i++)
                #pragma unroll
                for (int j = 0; j < 4; j++)
                    acc[i][j] += a[i] * b[j];
        }
        __syncthreads();
    }
    #pragma unroll
    for (int i = 0; i < 4; i++) {
        int s = slots[ty*4 + i];
        if (s < 0) continue;
        #pragma unroll
        for (int j = 0; j < 4; j++) {
            int gn = n0 + tx*4 + j;
            g_eo[(long long)s * 1024 + gn] = acc[i][j] + b2[e * 1024 + gn];
        }
    }
}

__global__ void combine_k(const float* __restrict__ x, float* __restrict__ out) {
    int idx = blockIdx.x * 256 + threadIdx.x;     // 0 .. 2048*1024-1
    int t = idx >> 10, d = idx & 1023;
    float v = x[idx];
    v += g_probs[2*t]     * g_eo[(long long)(2*t)     * 1024 + d];
    v += g_probs[2*t + 1] * g_eo[(long long)(2*t + 1) * 1024 + d];
    out[idx] = v;
}

// ---------------- launcher ----------------
extern "C" void kernel_launch(void* const* d_in, const int* in_sizes, int n_in,
                              void* d_out, int out_size) {
    const float* q        = (const float*)d_in[0];
    const float* kv       = (const float*)d_in[1];
    const float* ln_cq_g  = (const float*)d_in[2];
    const float* ln_cq_b  = (const float*)d_in[3];
    const float* ln_ckv_g = (const float*)d_in[4];
    const float* ln_ckv_b = (const float*)d_in[5];
    const float* ln_s_g   = (const float*)d_in[6];
    const float* ln_s_b   = (const float*)d_in[7];
    const float* ln_m_g   = (const float*)d_in[8];
    const float* ln_m_b   = (const float*)d_in[9];
    const float* ca_in_w  = (const float*)d_in[10];
    const float* ca_in_b  = (const float*)d_in[11];
    const float* ca_out_w = (const float*)d_in[12];
    const float* ca_out_b = (const float*)d_in[13];
    const float* sa_in_w  = (const float*)d_in[14];
    const float* sa_in_b  = (const float*)d_in[15];
    const float* sa_out_w = (const float*)d_in[16];
    const float* sa_out_b = (const float*)d_in[17];
    const float* moe_rw   = (const float*)d_in[18];
    const float* moe_rb   = (const float*)d_in[19];
    const float* moe_nw   = (const float*)d_in[20];
    const float* moe_nb   = (const float*)d_in[21];
    const float* moe_w1   = (const float*)d_in[22];
    const float* moe_b1   = (const float*)d_in[23];
    const float* moe_w2   = (const float*)d_in[24];
    const float* moe_b2   = (const float*)d_in[25];
    float* out = (float*)d_out;

    float *p_x, *p_ln1, *p_lnkv, *p_qp, *p_kvp, *p_scores, *p_ao;
    cudaGetSymbolAddress((void**)&p_x,      g_x);
    cudaGetSymbolAddress((void**)&p_ln1,    g_ln1);
    cudaGetSymbolAddress((void**)&p_lnkv,   g_lnkv);
    cudaGetSymbolAddress((void**)&p_qp,     g_qp);
    cudaGetSymbolAddress((void**)&p_kvp,    g_kvp);
    cudaGetSymbolAddress((void**)&p_scores, g_scores);
    cudaGetSymbolAddress((void**)&p_ao,     g_ao);

    const long long ZL = 0;

    // ===== Cross-attention =====
    ln_k<<<TQ, 256>>>(q,  p_ln1,  ln_cq_g,  ln_cq_b);
    ln_k<<<TKV, 256>>>(kv, p_lnkv, ln_ckv_g, ln_ckv_b);

    // q proj: [2048,1024] = ln(q) @ Wq^T + bq
    gemm_k<true><<<dim3(16, 32, 1), 256>>>(p_ln1, 1024, ZL, ZL,
        ca_in_w, 1024, ZL, ZL, p_qp, 1024, ZL, ZL,
        TQ, 1024, 1024, 1, ca_in_b, 1.0f, nullptr);
    // kv proj: [4096,2048] = ln(kv) @ [Wk;Wv]^T + [bk;bv]
    gemm_k<true><<<dim3(32, 64, 1), 256>>>(p_lnkv, 1024, ZL, ZL,
        ca_in_w + 1024*1024, 1024, ZL, ZL, p_kvp, 2048, ZL, ZL,
        TKV, 2048, 1024, 1, ca_in_b + 1024, 1.0f, nullptr);
    // scores = Q K^T / 8 : batch 32 (b,h), M=1024,N=2048,K=64
    gemm_k<true><<<dim3(32, 16, 32), 256>>>(
        p_qp, 1024, (long long)NQv*1024, 64,
        p_kvp, 2048, (long long)NKVv*2048, 64,
        p_scores, 2048, (long long)Hv*NQv*NKVv, (long long)NQv*NKVv,
        1024, 2048, 64, 16, nullptr, 0.125f, nullptr);
    softmax_k<<<Bv*Hv*NQv, 256>>>(p_scores, 2048);
    // O = P V : M=1024,N=64,K=2048
    gemm_k<false><<<dim3(1, 16, 32), 256>>>(
        p_scores, 2048, (long long)Hv*NQv*NKVv, (long long)NQv*NKVv,
        p_kvp + 1024, 2048, (long long)NKVv*2048, 64,
        p_ao, 1024, (long long)NQv*1024, 64,
        1024, 64, 2048, 16, nullptr, 1.0f, nullptr);
    // out proj + residual(q) -> x
    gemm_k<true><<<dim3(16, 32, 1), 256>>>(p_ao, 1024, ZL, ZL,
        ca_out_w, 1024, ZL, ZL, p_x, 1024, ZL, ZL,
        TQ, 1024, 1024, 1, ca_out_b, 1.0f, q);

    // ===== Self-attention =====
    ln_k<<<TQ, 256>>>(p_x, p_ln1, ln_s_g, ln_s_b);
    // qkv proj: [2048,3072]
    gemm_k<true><<<dim3(48, 32, 1), 256>>>(p_ln1, 1024, ZL, ZL,
        sa_in_w, 1024, ZL, ZL, p_kvp, 3072, ZL, ZL,
        TQ, 3072, 1024, 1, sa_in_b, 1.0f, nullptr);
    // scores: M=N=1024, K=64
    gemm_k<true><<<dim3(16, 16, 32), 256>>>(
        p_kvp, 3072, (long long)NQv*3072, 64,
        p_kvp + 1024, 3072, (long long)NQv*3072, 64,
        p_scores, 1024, (long long)Hv*NQv*NQv, (long long)NQv*NQv,
        1024, 1024, 64, 16, nullptr, 0.125f, nullptr);
    softmax_k<<<Bv*Hv*NQv, 256>>>(p_scores, 1024);
    gemm_k<false><<<dim3(1, 16, 32), 256>>>(
        p_scores, 1024, (long long)Hv*NQv*NQv, (long long)NQv*NQv,
        p_kvp + 2048, 3072, (long long)NQv*3072, 64,
        p_ao, 1024, (long long)NQv*1024, 64,
        1024, 64, 1024, 16, nullptr, 1.0f, nullptr);
    gemm_k<true><<<dim3(16, 32, 1), 256>>>(p_ao, 1024, ZL, ZL,
        sa_out_w, 1024, ZL, ZL, p_x, 1024, ZL, ZL,
        TQ, 1024, 1024, 1, sa_out_b, 1.0f, p_x);

    // ===== MoE =====
    ln_k<<<TQ, 256>>>(p_x, p_ln1, ln_m_g, ln_m_b);
    zero_counts_k<<<1, 32>>>();
    router_k<<<TQ, 256>>>(p_ln1, moe_rw, moe_rb, moe_nw, moe_nb);
    moe_gemm1<<<dim3(64, 32, 8), 256>>>(p_ln1, moe_w1, moe_b1);
    moe_gemm2<<<dim3(16, 32, 8), 256>>>(moe_w2, moe_b2);
    combine_k<<<(TQ*Dv)/256, 256>>>(p_x, out);
}

// round 4
// speedup vs baseline: 1.5494x; 1.5494x over previous
#include <cuda_runtime.h>
#include <math.h>
#include <stdint.h>

// Problem dims
#define Bv    2
#define NQv   1024
#define NKVv  2048
#define Dv    1024
#define Hv    16
#define DHv   64
#define Ev    8
#define FFv   4096
#define TQ    (Bv*NQv)
#define TKV   (Bv*NKVv)
#define MAXTOK 2048

// ---------------- scratch ----------------
__device__ float g_x[TQ*Dv];
__device__ float g_ln1[TQ*Dv];
__device__ float g_lnkv[TKV*Dv];
__device__ float g_qp[TQ*Dv];
__device__ float g_kvp[TKV*2048];
__device__ float g_scores[(size_t)Bv*Hv*NQv*NKVv];
__device__ float g_ao[TQ*Dv];
__device__ float g_h[(size_t)TQ*2*FFv];
__device__ float g_eo[(size_t)TQ*2*Dv];
__device__ float g_probs[TQ*2];
__device__ int   g_counts[Ev];
__device__ int   g_elist[Ev*MAXTOK];

// ---------------- layernorm ----------------
__global__ void ln_k(const float* __restrict__ x, float* __restrict__ y,
                     const float* __restrict__ g, const float* __restrict__ b) {
    long row = blockIdx.x;
    const float* xr = x + row * 1024;
    float* yr = y + row * 1024;
    __shared__ float sm[1024];
    __shared__ float red[256];
    int tid = threadIdx.x;
    float s = 0.f;
    #pragma unroll
    for (int i = 0; i < 4; i++) { float v = xr[tid + (i<<8)]; sm[tid + (i<<8)] = v; s += v; }
    red[tid] = s; __syncthreads();
    for (int st = 128; st > 0; st >>= 1) { if (tid < st) red[tid] += red[tid + st]; __syncthreads(); }
    float mean = red[0] * (1.0f/1024.0f); __syncthreads();
    float s2 = 0.f;
    #pragma unroll
    for (int i = 0; i < 4; i++) { float d = sm[tid + (i<<8)] - mean; s2 += d*d; }
    red[tid] = s2; __syncthreads();
    for (int st = 128; st > 0; st >>= 1) { if (tid < st) red[tid] += red[tid + st]; __syncthreads(); }
    float var = red[0] * (1.0f/1024.0f);
    float rstd = rsqrtf(var + 1e-5f);
    #pragma unroll
    for (int i = 0; i < 4; i++) { int c = tid + (i<<8); yr[c] = (sm[c]-mean)*rstd*g[c] + b[c]; }
}

// ---------------- softmax ----------------
__global__ void softmax_k(float* __restrict__ S, int L) {
    float* r = S + (size_t)blockIdx.x * L;
    int tid = threadIdx.x;
    __shared__ float red[256];
    int cnt = L >> 8;
    float v[8];
    float mx = -3.4e38f;
    for (int i = 0; i < cnt; i++) { v[i] = r[tid + (i<<8)]; mx = fmaxf(mx, v[i]); }
    red[tid] = mx; __syncthreads();
    for (int st = 128; st > 0; st >>= 1) { if (tid < st) red[tid] = fmaxf(red[tid], red[tid+st]); __syncthreads(); }
    mx = red[0]; __syncthreads();
    float sum = 0.f;
    for (int i = 0; i < cnt; i++) { v[i] = expf(v[i]-mx); sum += v[i]; }
    red[tid] = sum; __syncthreads();
    for (int st = 128; st > 0; st >>= 1) { if (tid < st) red[tid] += red[tid+st]; __syncthreads(); }
    float inv = 1.0f / red[0];
    for (int i = 0; i < cnt; i++) r[tid + (i<<8)] = v[i]*inv;
}

// ---------------- tf32 mma helpers ----------------
__device__ __forceinline__ unsigned f2tf(float x) {
    unsigned r; asm("cvt.rna.tf32.f32 %0, %1;" : "=r"(r) : "f"(x)); return r;
}
__device__ __forceinline__ void split_tf32(float x, unsigned& h, unsigned& l) {
    h = f2tf(x);
    l = f2tf(x - __uint_as_float(h));
}
__device__ __forceinline__ void mma8(float* c, const unsigned* a, const unsigned* b) {
    asm volatile("mma.sync.aligned.m16n8k8.row.col.f32.tf32.tf32.f32 "
        "{%0,%1,%2,%3},{%4,%5,%6,%7},{%8,%9},{%0,%1,%2,%3};"
        : "+f"(c[0]), "+f"(c[1]), "+f"(c[2]), "+f"(c[3])
        : "r"(a[0]), "r"(a[1]), "r"(a[2]), "r"(a[3]), "r"(b[0]), "r"(b[1]));
}

// ---------------- 3xTF32 tensor-core GEMM ----------------
// C[M,N] = alpha * A[M,K] * op(B) + bias + res
// BT=true : B is [N,K] row-major;  BT=false: B is [K,N] row-major
// Block tile 128x64, BK=16, 8 warps of 32x32 warp tiles.
template<bool BT>
__global__ __launch_bounds__(256, 2) void mma_gemm(
    const float* __restrict__ A, int lda, long long sAo, long long sAi,
    const float* __restrict__ B, int ldb, long long sBo, long long sBi,
    float* __restrict__ C, int ldc, long long sCo, long long sCi,
    int M, int N, int K, int inner,
    const float* __restrict__ bias, float alpha, const float* __restrict__ res)
{
    int z = blockIdx.z;
    int zo = z / inner, zi = z - zo * inner;
    A += zo * sAo + zi * sAi;
    B += zo * sBo + zi * sBi;
    C += zo * sCo + zi * sCi;
    if (res) res += zo * sCo + zi * sCi;

    __shared__ float As[128*20];      // [m][k] stride 20
    __shared__ float Bs[1280];        // BT: [n][k] stride 20 ; !BT: [k][n] stride 72

    int tid = threadIdx.x, lane = tid & 31, warp = tid >> 5;
    int g = lane >> 2, tig = lane & 3;
    int wm = (warp & 3) * 32, wn = (warp >> 2) * 32;
    int m0 = blockIdx.y * 128, n0 = blockIdx.x * 64;

    float c[2][4][4] = {};

    for (int k0 = 0; k0 < K; k0 += 16) {
        // ---- stage A: 128x16 ----
        #pragma unroll
        for (int i = 0; i < 2; i++) {
            int f = tid + (i << 8);
            int r = f >> 2, kq = (f & 3) << 2;
            int gm = m0 + r;
            float4 v = make_float4(0.f, 0.f, 0.f, 0.f);
            if (gm < M) v = *(const float4*)&A[(long long)gm * lda + k0 + kq];
            As[r*20+kq] = v.x; As[r*20+kq+1] = v.y; As[r*20+kq+2] = v.z; As[r*20+kq+3] = v.w;
        }
        // ---- stage B: 64x16 ----
        if (BT) {
            int n = tid >> 2, kq = (tid & 3) << 2;
            float4 v = *(const float4*)&B[(long long)(n0 + n) * ldb + k0 + kq];
            Bs[n*20+kq] = v.x; Bs[n*20+kq+1] = v.y; Bs[n*20+kq+2] = v.z; Bs[n*20+kq+3] = v.w;
        } else {
            int kk = tid >> 4, nq = (tid & 15) << 2;
            float4 v = *(const float4*)&B[(long long)(k0 + kk) * ldb + n0 + nq];
            Bs[kk*72+nq] = v.x; Bs[kk*72+nq+1] = v.y; Bs[kk*72+nq+2] = v.z; Bs[kk*72+nq+3] = v.w;
        }
        __syncthreads();

        #pragma unroll
        for (int kk = 0; kk < 16; kk += 8) {
            unsigned ah[2][4], al[2][4];
            #pragma unroll
            for (int mt = 0; mt < 2; mt++) {
                int rb = wm + mt*16 + g;
                float x0 = As[rb*20 + kk + tig];
                float x1 = As[(rb+8)*20 + kk + tig];
                float x2 = As[rb*20 + kk + tig + 4];
                float x3 = As[(rb+8)*20 + kk + tig + 4];
                split_tf32(x0, ah[mt][0], al[mt][0]);
                split_tf32(x1, ah[mt][1], al[mt][1]);
                split_tf32(x2, ah[mt][2], al[mt][2]);
                split_tf32(x3, ah[mt][3], al[mt][3]);
            }
            unsigned bh[4][2], bl[4][2];
            #pragma unroll
            for (int nt = 0; nt < 4; nt++) {
                int nb = wn + nt*8 + g;
                float y0, y1;
                if (BT) { y0 = Bs[nb*20 + kk + tig];  y1 = Bs[nb*20 + kk + tig + 4]; }
                else    { y0 = Bs[(kk+tig)*72 + nb];  y1 = Bs[(kk+tig+4)*72 + nb]; }
                split_tf32(y0, bh[nt][0], bl[nt][0]);
                split_tf32(y1, bh[nt][1], bl[nt][1]);
            }
            #pragma unroll
            for (int mt = 0; mt < 2; mt++)
                #pragma unroll
                for (int nt = 0; nt < 4; nt++) {
                    mma8(c[mt][nt], ah[mt], bh[nt]);
                    mma8(c[mt][nt], ah[mt], bl[nt]);
                    mma8(c[mt][nt], al[mt], bh[nt]);
                }
        }
        __syncthreads();
    }

    // ---- epilogue ----
    #pragma unroll
    for (int mt = 0; mt < 2; mt++) {
        int r0 = m0 + wm + mt*16 + g;
        #pragma unroll
        for (int nt = 0; nt < 4; nt++) {
            int col = n0 + wn + nt*8 + tig*2;
            float bv0 = bias ? bias[col]   : 0.f;
            float bv1 = bias ? bias[col+1] : 0.f;
            if (r0 < M) {
                float v0 = alpha*c[mt][nt][0] + bv0;
                float v1 = alpha*c[mt][nt][1] + bv1;
                if (res) { v0 += res[(long long)r0*ldc + col]; v1 += res[(long long)r0*ldc + col + 1]; }
                C[(long long)r0*ldc + col]     = v0;
                C[(long long)r0*ldc + col + 1] = v1;
            }
            int r1 = r0 + 8;
            if (r1 < M) {
                float v2 = alpha*c[mt][nt][2] + bv0;
                float v3 = alpha*c[mt][nt][3] + bv1;
                if (res) { v2 += res[(long long)r1*ldc + col]; v3 += res[(long long)r1*ldc + col + 1]; }
                C[(long long)r1*ldc + col]     = v2;
                C[(long long)r1*ldc + col + 1] = v3;
            }
        }
    }
}

// ---------------- JAX threefry2x32 / normal ----------------
__device__ __forceinline__ void threefry42(unsigned c0, unsigned c1, unsigned& o0, unsigned& o1) {
    const unsigned k0 = 0u, k1 = 42u;
    const unsigned k2 = 0x1BD11BDAu ^ k0 ^ k1;
    unsigned x0 = c0 + k0, x1 = c1 + k1;
#define TF_R(r) { x0 += x1; x1 = (x1 << r) | (x1 >> (32 - r)); x1 ^= x0; }
    TF_R(13) TF_R(15) TF_R(26) TF_R(6)   x0 += k1; x1 += k2 + 1u;
    TF_R(17) TF_R(29) TF_R(16) TF_R(24)  x0 += k2; x1 += k0 + 2u;
    TF_R(13) TF_R(15) TF_R(26) TF_R(6)   x0 += k0; x1 += k1 + 3u;
    TF_R(17) TF_R(29) TF_R(16) TF_R(24)  x0 += k1; x1 += k2 + 4u;
    TF_R(13) TF_R(15) TF_R(26) TF_R(6)   x0 += k2; x1 += k0 + 5u;
#undef TF_R
    o0 = x0; o1 = x1;
}

__device__ __forceinline__ float erfinv_f(float x) {
    float w = -log1pf(__fmul_rn(-x, x));
    float p;
    if (w < 5.0f) {
        w = __fadd_rn(w, -2.5f);
        p = 2.81022636e-08f;
        p = __fadd_rn(__fmul_rn(p, w),  3.43273939e-07f);
        p = __fadd_rn(__fmul_rn(p, w), -3.5233877e-06f);
        p = __fadd_rn(__fmul_rn(p, w), -4.39150654e-06f);
        p = __fadd_rn(__fmul_rn(p, w),  0.00021858087f);
        p = __fadd_rn(__fmul_rn(p, w), -0.00125372503f);
        p = __fadd_rn(__fmul_rn(p, w), -0.00417768164f);
        p = __fadd_rn(__fmul_rn(p, w),  0.246640727f);
        p = __fadd_rn(__fmul_rn(p, w),  1.50140941f);
    } else {
        w = __fadd_rn(sqrtf(w), -3.0f);
        p = -0.000200214257f;
        p = __fadd_rn(__fmul_rn(p, w),  0.000100950558f);
        p = __fadd_rn(__fmul_rn(p, w),  0.00134934322f);
        p = __fadd_rn(__fmul_rn(p, w), -0.00367342844f);
        p = __fadd_rn(__fmul_rn(p, w),  0.00573950773f);
        p = __fadd_rn(__fmul_rn(p, w), -0.0076224613f);
        p = __fadd_rn(__fmul_rn(p, w),  0.00943887047f);
        p = __fadd_rn(__fmul_rn(p, w),  1.00167406f);
        p = __fadd_rn(__fmul_rn(p, w),  2.83297682f);
    }
    return __fmul_rn(p, x);
}

// partitionable threefry: counter (0, i), bits = out0 ^ out1
__device__ __forceinline__ float jax_normal(int i) {
    unsigned o0, o1;
    threefry42(0u, (unsigned)i, o0, o1);
    unsigned bits = o0 ^ o1;
    unsigned fb = (bits >> 9) | 0x3f800000u;
    float u01 = __fadd_rn(__uint_as_float(fb), -1.0f);
    const float lo = -0.99999994f;
    float u = __fadd_rn(__fmul_rn(u01, 2.0f), lo);
    u = fmaxf(lo, u);
    return __fmul_rn(1.41421354f, erfinv_f(u));
}

// ---------------- MoE router ----------------
__global__ void zero_counts_k() { if (threadIdx.x < Ev) g_counts[threadIdx.x] = 0; }

__global__ void router_k(const float* __restrict__ xm,
                         const float* __restrict__ rw, const float* __restrict__ rb,
                         const float* __restrict__ nw, const float* __restrict__ nb) {
    int t = blockIdx.x;
    int tid = threadIdx.x;
    int w = tid >> 5, lane = tid & 31;
    __shared__ float sl[8], sn[8];
    const float* xr = xm + (long long)t * 1024;
    const float* rwe = rw + w * 1024;
    const float* nwe = nw + w * 1024;
    float sr = 0.f, s_n = 0.f;
    for (int d = lane; d < 1024; d += 32) {
        float xv = xr[d];
        sr  += xv * rwe[d];
        s_n += xv * nwe[d];
    }
    #pragma unroll
    for (int o = 16; o; o >>= 1) {
        sr  += __shfl_down_sync(0xffffffffu, sr, o);
        s_n += __shfl_down_sync(0xffffffffu, s_n, o);
    }
    if (lane == 0) { sl[w] = sr + rb[w]; sn[w] = s_n + nb[w]; }
    __syncthreads();
    if (tid == 0) {
        float noisy[8];
        #pragma unroll
        for (int e = 0; e < 8; e++) {
            float nrm = jax_normal(t * 8 + e);
            float zz = sn[e];
            float sp = fmaxf(zz, 0.f) + log1pf(expf(-fabsf(zz)));
            noisy[e] = sl[e] + nrm * sp;
        }
        int i1 = 0;
        #pragma unroll
        for (int e = 1; e < 8; e++) if (noisy[e] > noisy[i1]) i1 = e;
        int i2 = (i1 == 0) ? 1 : 0;
        #pragma unroll
        for (int e = 0; e < 8; e++) if (e != i1 && noisy[e] > noisy[i2]) i2 = e;
        float mx = noisy[i1];
        float e1 = expf(noisy[i1] - mx);
        float e2 = expf(noisy[i2] - mx);
        float Z  = e1 + e2;
        g_probs[2*t]   = e1 / Z;
        g_probs[2*t+1] = e2 / Z;
        int p1 = atomicAdd(&g_counts[i1], 1); g_elist[i1 * MAXTOK + p1] = 2*t;
        int p2 = atomicAdd(&g_counts[i2], 1); g_elist[i2 * MAXTOK + p2] = 2*t + 1;
    }
}

// ---------------- MoE tensor-core GEMMs ----------------
// GEMM1: h[slot] = gelu(xm[tok] @ w1[e] + b1[e])   (w1: [K=1024][N=4096])
__global__ __launch_bounds__(256, 2) void moe_mma1(const float* __restrict__ xm,
                                                   const float* __restrict__ w1,
                                                   const float* __restrict__ b1) {
    int e = blockIdx.z;
    int cnt = g_counts[e];
    int m0 = blockIdx.y * 128;
    if (m0 >= cnt) return;
    int n0 = blockIdx.x * 64;

    __shared__ int slots[128];
    __shared__ float As[128*20];
    __shared__ float Bs[16*72];

    int tid = threadIdx.x, lane = tid & 31, warp = tid >> 5;
    int g = lane >> 2, tig = lane & 3;
    int wm = (warp & 3) * 32, wn = (warp >> 2) * 32;
    if (tid < 128) slots[tid] = (m0 + tid < cnt) ? g_elist[e * MAXTOK + m0 + tid] : -1;
    __syncthreads();

    const float* Be = w1 + (long long)e * 1024 * 4096;
    float c[2][4][4] = {};

    for (int k0 = 0; k0 < 1024; k0 += 16) {
        #pragma unroll
        for (int i = 0; i < 2; i++) {
            int f = tid + (i << 8);
            int r = f >> 2, kq = (f & 3) << 2;
            int s = slots[r];
            float4 v = make_float4(0.f, 0.f, 0.f, 0.f);
            if (s >= 0) v = *(const float4*)&xm[(long long)(s >> 1) * 1024 + k0 + kq];
            As[r*20+kq] = v.x; As[r*20+kq+1] = v.y; As[r*20+kq+2] = v.z; As[r*20+kq+3] = v.w;
        }
        {
            int kk = tid >> 4, nq = (tid & 15) << 2;
            float4 v = *(const float4*)&Be[(long long)(k0 + kk) * 4096 + n0 + nq];
            Bs[kk*72+nq] = v.x; Bs[kk*72+nq+1] = v.y; Bs[kk*72+nq+2] = v.z; Bs[kk*72+nq+3] = v.w;
        }
        __syncthreads();
        #pragma unroll
        for (int kk = 0; kk < 16; kk += 8) {
            unsigned ah[2][4], al[2][4];
            #pragma unroll
            for (int mt = 0; mt < 2; mt++) {
                int rb = wm + mt*16 + g;
                split_tf32(As[rb*20 + kk + tig],       ah[mt][0], al[mt][0]);
                split_tf32(As[(rb+8)*20 + kk + tig],   ah[mt][1], al[mt][1]);
                split_tf32(As[rb*20 + kk + tig + 4],   ah[mt][2], al[mt][2]);
                split_tf32(As[(rb+8)*20 + kk + tig+4], ah[mt][3], al[mt][3]);
            }
            unsigned bh[4][2], bl[4][2];
            #pragma unroll
            for (int nt = 0; nt < 4; nt++) {
                int nb = wn + nt*8 + g;
                split_tf32(Bs[(kk+tig)*72 + nb],   bh[nt][0], bl[nt][0]);
                split_tf32(Bs[(kk+tig+4)*72 + nb], bh[nt][1], bl[nt][1]);
            }
            #pragma unroll
            for (int mt = 0; mt < 2; mt++)
                #pragma unroll
                for (int nt = 0; nt < 4; nt++) {
                    mma8(c[mt][nt], ah[mt], bh[nt]);
                    mma8(c[mt][nt], ah[mt], bl[nt]);
                    mma8(c[mt][nt], al[mt], bh[nt]);
                }
        }
        __syncthreads();
    }

    #pragma unroll
    for (int mt = 0; mt < 2; mt++) {
        int lr0 = wm + mt*16 + g;
        int s0 = slots[lr0], s1 = slots[lr0 + 8];
        #pragma unroll
        for (int nt = 0; nt < 4; nt++) {
            int col = n0 + wn + nt*8 + tig*2;
            float bv0 = b1[e*4096 + col], bv1 = b1[e*4096 + col + 1];
            if (s0 >= 0) {
                float v0 = c[mt][nt][0] + bv0;
                float v1 = c[mt][nt][1] + bv1;
                v0 = 0.5f * v0 * (1.0f + erff(v0 * 0.70710677f));
                v1 = 0.5f * v1 * (1.0f + erff(v1 * 0.70710677f));
                g_h[(long long)s0*4096 + col]     = v0;
                g_h[(long long)s0*4096 + col + 1] = v1;
            }
            if (s1 >= 0) {
                float v2 = c[mt][nt][2] + bv0;
                float v3 = c[mt][nt][3] + bv1;
                v2 = 0.5f * v2 * (1.0f + erff(v2 * 0.70710677f));
                v3 = 0.5f * v3 * (1.0f + erff(v3 * 0.70710677f));
                g_h[(long long)s1*4096 + col]     = v2;
                g_h[(long long)s1*4096 + col + 1] = v3;
            }
        }
    }
}

// GEMM2: eo[slot] = h[slot] @ w2[e] + b2[e]   (w2: [K=4096][N=1024])
__global__ __launch_bounds__(256, 2) void moe_mma2(const float* __restrict__ w2,
                                                   const float* __restrict__ b2) {
    int e = blockIdx.z;
    int cnt = g_counts[e];
    int m0 = blockIdx.y * 128;
    if (m0 >= cnt) return;
    int n0 = blockIdx.x * 64;

    __shared__ int slots[128];
    __shared__ float As[128*20];
    __shared__ float Bs[16*72];

    int tid = threadIdx.x, lane = tid & 31, warp = tid >> 5;
    int g = lane >> 2, tig = lane & 3;
    int wm = (warp & 3) * 32, wn = (warp >> 2) * 32;
    if (tid < 128) slots[tid] = (m0 + tid < cnt) ? g_elist[e * MAXTOK + m0 + tid] : -1;
    __syncthreads();

    const float* Be = w2 + (long long)e * 4096 * 1024;
    float c[2][4][4] = {};

    for (int k0 = 0; k0 < 4096; k0 += 16) {
        #pragma unroll
        for (int i = 0; i < 2; i++) {
            int f = tid + (i << 8);
            int r = f >> 2, kq = (f & 3) << 2;
            int s = slots[r];
            float4 v = make_float4(0.f, 0.f, 0.f, 0.f);
            if (s >= 0) v = *(const float4*)&g_h[(long long)s * 4096 + k0 + kq];
            As[r*20+kq] = v.x; As[r*20+kq+1] = v.y; As[r*20+kq+2] = v.z; As[r*20+kq+3] = v.w;
        }
        {
            int kk = tid >> 4, nq = (tid & 15) << 2;
            float4 v = *(const float4*)&Be[(long long)(k0 + kk) * 1024 + n0 + nq];
            Bs[kk*72+nq] = v.x; Bs[kk*72+nq+1] = v.y; Bs[kk*72+nq+2] = v.z; Bs[kk*72+nq+3] = v.w;
        }
        __syncthreads();
        #pragma unroll
        for (int kk = 0; kk < 16; kk += 8) {
            unsigned ah[2][4], al[2][4];
            #pragma unroll
            for (int mt = 0; mt < 2; mt++) {
                int rb = wm + mt*16 + g;
                split_tf32(As[rb*20 + kk + tig],       ah[mt][0], al[mt][0]);
                split_tf32(As[(rb+8)*20 + kk + tig],   ah[mt][1], al[mt][1]);
                split_tf32(As[rb*20 + kk + tig + 4],   ah[mt][2], al[mt][2]);
                split_tf32(As[(rb+8)*20 + kk + tig+4], ah[mt][3], al[mt][3]);
            }
            unsigned bh[4][2], bl[4][2];
            #pragma unroll
            for (int nt = 0; nt < 4; nt++) {
                int nb = wn + nt*8 + g;
                split_tf32(Bs[(kk+tig)*72 + nb],   bh[nt][0], bl[nt][0]);
                split_tf32(Bs[(kk+tig+4)*72 + nb], bh[nt][1], bl[nt][1]);
            }
            #pragma unroll
            for (int mt = 0; mt < 2; mt++)
                #pragma unroll
                for (int nt = 0; nt < 4; nt++) {
                    mma8(c[mt][nt], ah[mt], bh[nt]);
                    mma8(c[mt][nt], ah[mt], bl[nt]);
                    mma8(c[mt][nt], al[mt], bh[nt]);
                }
        }
        __syncthreads();
    }

    #pragma unroll
    for (int mt = 0; mt < 2; mt++) {
        int lr0 = wm + mt*16 + g;
        int s0 = slots[lr0], s1 = slots[lr0 + 8];
        #pragma unroll
        for (int nt = 0; nt < 4; nt++) {
            int col = n0 + wn + nt*8 + tig*2;
            float bv0 = b2[e*1024 + col], bv1 = b2[e*1024 + col + 1];
            if (s0 >= 0) {
                g_eo[(long long)s0*1024 + col]     = c[mt][nt][0] + bv0;
                g_eo[(long long)s0*1024 + col + 1] = c[mt][nt][1] + bv1;
            }
            if (s1 >= 0) {
                g_eo[(long long)s1*1024 + col]     = c[mt][nt][2] + bv0;
                g_eo[(long long)s1*1024 + col + 1] = c[mt][nt][3] + bv1;
            }
        }
    }
}

__global__ void combine_k(const float* __restrict__ x, float* __restrict__ out) {
    int idx = blockIdx.x * 256 + threadIdx.x;
    int t = idx >> 10, d = idx & 1023;
    float v = x[idx];
    v += g_probs[2*t]     * g_eo[(long long)(2*t)     * 1024 + d];
    v += g_probs[2*t + 1] * g_eo[(long long)(2*t + 1) * 1024 + d];
    out[idx] = v;
}

// ---------------- launcher ----------------
extern "C" void kernel_launch(void* const* d_in, const int* in_sizes, int n_in,
                              void* d_out, int out_size) {
    const float* q        = (const float*)d_in[0];
    const float* kv       = (const float*)d_in[1];
    const float* ln_cq_g  = (const float*)d_in[2];
    const float* ln_cq_b  = (const float*)d_in[3];
    const float* ln_ckv_g = (const float*)d_in[4];
    const float* ln_ckv_b = (const float*)d_in[5];
    const float* ln_s_g   = (const float*)d_in[6];
    const float* ln_s_b   = (const float*)d_in[7];
    const float* ln_m_g   = (const float*)d_in[8];
    const float* ln_m_b   = (const float*)d_in[9];
    const float* ca_in_w  = (const float*)d_in[10];
    const float* ca_in_b  = (const float*)d_in[11];
    const float* ca_out_w = (const float*)d_in[12];
    const float* ca_out_b = (const float*)d_in[13];
    const float* sa_in_w  = (const float*)d_in[14];
    const float* sa_in_b  = (const float*)d_in[15];
    const float* sa_out_w = (const float*)d_in[16];
    const float* sa_out_b = (const float*)d_in[17];
    const float* moe_rw   = (const float*)d_in[18];
    const float* moe_rb   = (const float*)d_in[19];
    const float* moe_nw   = (const float*)d_in[20];
    const float* moe_nb   = (const float*)d_in[21];
    const float* moe_w1   = (const float*)d_in[22];
    const float* moe_b1   = (const float*)d_in[23];
    const float* moe_w2   = (const float*)d_in[24];
    const float* moe_b2   = (const float*)d_in[25];
    float* out = (float*)d_out;

    float *p_x, *p_ln1, *p_lnkv, *p_qp, *p_kvp, *p_scores, *p_ao;
    cudaGetSymbolAddress((void**)&p_x,      g_x);
    cudaGetSymbolAddress((void**)&p_ln1,    g_ln1);
    cudaGetSymbolAddress((void**)&p_lnkv,   g_lnkv);
    cudaGetSymbolAddress((void**)&p_qp,     g_qp);
    cudaGetSymbolAddress((void**)&p_kvp,    g_kvp);
    cudaGetSymbolAddress((void**)&p_scores, g_scores);
    cudaGetSymbolAddress((void**)&p_ao,     g_ao);

    const long long ZL = 0;

    // ===== Cross-attention =====
    ln_k<<<TQ, 256>>>(q,  p_ln1,  ln_cq_g,  ln_cq_b);
    ln_k<<<TKV, 256>>>(kv, p_lnkv, ln_ckv_g, ln_ckv_b);

    mma_gemm<true><<<dim3(16, 16, 1), 256>>>(p_ln1, 1024, ZL, ZL,
        ca_in_w, 1024, ZL, ZL, p_qp, 1024, ZL, ZL,
        TQ, 1024, 1024, 1, ca_in_b, 1.0f, nullptr);
    mma_gemm<true><<<dim3(32, 32, 1), 256>>>(p_lnkv, 1024, ZL, ZL,
        ca_in_w + 1024*1024, 1024, ZL, ZL, p_kvp, 2048, ZL, ZL,
        TKV, 2048, 1024, 1, ca_in_b + 1024, 1.0f, nullptr);
    mma_gemm<true><<<dim3(32, 8, 32), 256>>>(
        p_qp, 1024, (long long)NQv*1024, 64,
        p_kvp, 2048, (long long)NKVv*2048, 64,
        p_scores, 2048, (long long)Hv*NQv*NKVv, (long long)NQv*NKVv,
        1024, 2048, 64, 16, nullptr, 0.125f, nullptr);
    softmax_k<<<Bv*Hv*NQv, 256>>>(p_scores, 2048);
    mma_gemm<false><<<dim3(1, 8, 32), 256>>>(
        p_scores, 2048, (long long)Hv*NQv*NKVv, (long long)NQv*NKVv,
        p_kvp + 1024, 2048, (long long)NKVv*2048, 64,
        p_ao, 1024, (long long)NQv*1024, 64,
        1024, 64, 2048, 16, nullptr, 1.0f, nullptr);
    mma_gemm<true><<<dim3(16, 16, 1), 256>>>(p_ao, 1024, ZL, ZL,
        ca_out_w, 1024, ZL, ZL, p_x, 1024, ZL, ZL,
        TQ, 1024, 1024, 1, ca_out_b, 1.0f, q);

    // ===== Self-attention =====
    ln_k<<<TQ, 256>>>(p_x, p_ln1, ln_s_g, ln_s_b);
    mma_gemm<true><<<dim3(48, 16, 1), 256>>>(p_ln1, 1024, ZL, ZL,
        sa_in_w, 1024, ZL, ZL, p_kvp, 3072, ZL, ZL,
        TQ, 3072, 1024, 1, sa_in_b, 1.0f, nullptr);
    mma_gemm<true><<<dim3(16, 8, 32), 256>>>(
        p_kvp, 3072, (long long)NQv*3072, 64,
        p_kvp + 1024, 3072, (long long)NQv*3072, 64,
        p_scores, 1024, (long long)Hv*NQv*NQv, (long long)NQv*NQv,
        1024, 1024, 64, 16, nullptr, 0.125f, nullptr);
    softmax_k<<<Bv*Hv*NQv, 256>>>(p_scores, 1024);
    mma_gemm<false><<<dim3(1, 8, 32), 256>>>(
        p_scores, 1024, (long long)Hv*NQv*NQv, (long long)NQv*NQv,
        p_kvp + 2048, 3072, (long long)NQv*3072, 64,
        p_ao, 1024, (long long)NQv*1024, 64,
        1024, 64, 1024, 16, nullptr, 1.0f, nullptr);
    mma_gemm<true><<<dim3(16, 16, 1), 256>>>(p_ao, 1024, ZL, ZL,
        sa_out_w, 1024, ZL, ZL, p_x, 1024, ZL, ZL,
        TQ, 1024, 1024, 1, sa_out_b, 1.0f, p_x);

    // ===== MoE =====
    ln_k<<<TQ, 256>>>(p_x, p_ln1, ln_m_g, ln_m_b);
    zero_counts_k<<<1, 32>>>();
    router_k<<<TQ, 256>>>(p_ln1, moe_rw, moe_rb, moe_nw, moe_nb);
    moe_mma1<<<dim3(64, 16, 8), 256>>>(p_ln1, moe_w1, moe_b1);
    moe_mma2<<<dim3(16, 16, 8), 256>>>(moe_w2, moe_b2);
    combine_k<<<(TQ*Dv)/256, 256>>>(p_x, out);
}